// round 8
// baseline (speedup 1.0000x reference)
#include <cuda_runtime.h>

// out[b,c,h,w] = max over 4 directional 3x3 Laplacians (zero-padded).
// out = max(s0,s1,s2,s3) - 2*c  (shared center term -> single FFMA).
// Software pipeline, DEPTH 2: row h+3 loads while row h computes
// (5 rotating 6-wide register windows) to cover the ~250-cycle L2 hit latency.
// RPT=16 -> grid of 1536 blocks = ONE full wave at 11 blocks/SM.

#define W   512
#define H   512
#define RPT 16   // rows per thread

__device__ __forceinline__ void load_row6(const float* __restrict__ img,
                                          int h, int w0, float a[6]) {
    if ((unsigned)h >= (unsigned)H) {
        #pragma unroll
        for (int i = 0; i < 6; i++) a[i] = 0.f;
        return;
    }
    const float* row = img + h * W;
    float4 v = __ldg((const float4*)(row + w0));
    a[1] = v.x; a[2] = v.y; a[3] = v.z; a[4] = v.w;
    a[0] = (w0 > 0)     ? __ldg(row + w0 - 1) : 0.f;  // same-line L1/L2 hit
    a[5] = (w0 + 4 < W) ? __ldg(row + w0 + 4) : 0.f;
}

__global__ __launch_bounds__(128, 11)
void maxlap_kernel(const float* __restrict__ x, float* __restrict__ out) {
    const int img = blockIdx.y;
    const int h0  = blockIdx.x * RPT;
    const int w0  = threadIdx.x * 4;   // 128 threads cover the full 512 row

    const float* in  = x   + (size_t)img * H * W;
    float*       dst = out + (size_t)img * H * W;

    // 5 rotating windows: at iteration rr,
    //   t = win[rr%5], m = win[(rr+1)%5], b = win[(rr+2)%5],
    //   row h0+rr+3 prefetches into win[(rr+4)%5]  (distance-2 pipeline).
    float win[5][6];
    load_row6(in, h0 - 1, w0, win[0]);
    load_row6(in, h0,     w0, win[1]);
    load_row6(in, h0 + 1, w0, win[2]);
    load_row6(in, h0 + 2, w0, win[3]);

    #pragma unroll
    for (int rr = 0; rr < RPT; rr++) {
        if (rr <= RPT - 3)
            load_row6(in, h0 + rr + 3, w0, win[(rr + 4) % 5]);  // prefetch D=2

        const float* t = win[ rr      % 5];
        const float* m = win[(rr + 1) % 5];
        const float* b = win[(rr + 2) % 5];

        float4 o;
        float* op = (float*)&o;
        #pragma unroll
        for (int i = 0; i < 4; i++) {
            const float s0 = m[i]     + m[i + 2];
            const float s1 = t[i + 1] + b[i + 1];
            const float s2 = t[i + 2] + b[i];
            const float s3 = t[i]     + b[i + 2];
            const float ms = fmaxf(fmaxf(s0, s1), fmaxf(s2, s3));
            op[i] = fmaf(-2.f, m[i + 1], ms);
        }
        // Streaming store: keep the L2-resident input from being evicted.
        __stcs((float4*)(dst + (h0 + rr) * W + w0), o);
    }
}

extern "C" void kernel_launch(void* const* d_in, const int* in_sizes, int n_in,
                              void* d_out, int out_size) {
    const float* x = (const float*)d_in[0];
    float* out = (float*)d_out;

    const int n_img = in_sizes[0] / (H * W);  // B*C = 48

    dim3 block(W / 4);               // 128 threads = one full row
    dim3 grid(H / RPT, n_img);       // 32 x 48 = 1536 blocks (single wave)
    maxlap_kernel<<<grid, block>>>(x, out);
}